// round 1
// baseline (speedup 1.0000x reference)
#include <cuda_runtime.h>

// HH_Synaptic: semi-implicit Hodgkin-Huxley + synapse integrator.
// z: (B=16, N=2000, L=1024) float32.  out: sigmoid((V - VT)/KP), same shape.
// One thread per (b, l) chain; 2000 serial steps per thread.

#define B_DIM 16
#define N_DIM 2000
#define L_DIM 1024

__global__ __launch_bounds__(128, 1)
void hh_synaptic_kernel(const float* __restrict__ z, float* __restrict__ out) {
    const int idx = blockIdx.x * blockDim.x + threadIdx.x;   // 0 .. 16383
    const int b = idx >> 10;
    const int l = idx & (L_DIM - 1);

    const float* zp = z   + (size_t)b * (N_DIM * L_DIM) + l;
    float*       op = out + (size_t)b * (N_DIM * L_DIM) + l;

    // State
    float V = -70.0f;
    float m = 0.0f, n = 0.0f, h = 1.0f, y = 0.0f;

    const float inv9  = 1.0f / 9.0f;
    const float inv12 = 1.0f / 12.0f;
    // aH * bH = 0.0625 * exp(-56/12) = const; aH = cAH / eH with eH = exp((V+34)/12)
    const float cAH = 0.25f * expf(-56.0f * inv12);

    // k = 0 output: sigmoid((V - VT)/KP) = sigmoid((V + 20)/3)
    {
        float s = (V + 20.0f) * (1.0f / 3.0f);
        op[0] = __fdividef(1.0f, 1.0f + __expf(-s));
    }

    float zc = zp[0];                 // z[k-1] for the first step (k=1)
    const float* zl = zp + L_DIM;     // points at z[k] (prefetch for next iter)
    float*       ol = op + L_DIM;     // points at out[k]

    #pragma unroll 2
    for (int k = 1; k < N_DIM; ++k) {
        // Prefetch z[k] (consumed next iteration). k <= N-1 so always in-bounds.
        float znext = __ldg(zl);

        // ---- conductances / implicit V update (uses z_prev = zc via y only) ----
        float m2   = m * m;
        float pow1 = 40.0f * (m2 * m) * h;          // GNA * m^3 * h
        float n2   = n * n;
        float pow2 = 35.0f * (n2 * n2);             // GK * n^4
        float gsum = pow1 + pow2 + (0.3f + y);      // + GL + GS*y   (GS=1)
        float G    = 0.01f * gsum;                  // DT/2 = 0.01
        float E    = fmaf(pow1, 55.0f, fmaf(pow2, -77.0f, -19.5f)); // GL*EL = -19.5; VS=0
        float Vn   = fmaf(V, 1.0f - G, 0.02f * (E + 1.0f)) / (1.0f + G); // DT*(E+IAPP)

        // ---- rate constants (3 exps via reciprocal pairing) ----
        float dv25 = Vn - 25.0f;
        float dv35 = Vn + 35.0f;
        float eN = expf(dv25 * inv9);               // exp((V-25)/9)
        float eM = expf(dv35 * inv9);               // exp((V+35)/9)
        float eH = expf((Vn + 34.0f) * inv12);      // exp((V+34)/12)

        float aN, bN;
        if (dv25 == 0.0f) { aN = 0.18f; bN = 0.08f; }   // reference's exact-equality patch
        else {
            float w = dv25 / (eN - 1.0f);
            aN = 0.02f  * w * eN;    // 0.02*(V-25)/(1-exp(-(V-25)/9))
            bN = 0.002f * w;         // -0.002*(V-25)/(1-exp((V-25)/9))
        }
        float aM, bM;
        if (dv35 == 0.0f) { aM = 1.638f; bM = 1.16f; }
        else {
            float w = dv35 / (eM - 1.0f);
            aM = 0.182f * w * eM;
            bM = 0.124f * w;
        }
        float bH = 0.25f * eH;
        float aH = cAH / eH;        // 0.25*exp(-(V+90)/12)

        // ---- semi-implicit gate updates: x' = (a*DT + (1-p)*x)/(1+p), p = DT/2*(a+b) ----
        float pM = 0.01f * (aM + bM);
        m = fmaf(aM, 0.02f, m - pM * m) / (1.0f + pM);
        float pN = 0.01f * (aN + bN);
        n = fmaf(aN, 0.02f, n - pN * n) / (1.0f + pN);
        float pH = 0.01f * (aH + bH);
        h = fmaf(aH, 0.02f, h - pH * h) / (1.0f + pH);

        // synapse: ady = A_D * z_prev (A_D = 1), A_R = 0.1
        float ady = zc;
        float pY  = 0.01f * (ady + 0.1f);
        y = fmaf(ady, 0.02f, y - pY * y) / (1.0f + pY);

        V = Vn;

        // output sigmoid: fast-math is safe here (no feedback into state)
        float s = (V + 20.0f) * (1.0f / 3.0f);
        *ol = __fdividef(1.0f, 1.0f + __expf(-s));

        zc = znext;
        zl += L_DIM;
        ol += L_DIM;
    }
}

extern "C" void kernel_launch(void* const* d_in, const int* in_sizes, int n_in,
                              void* d_out, int out_size) {
    const float* z = (const float*)d_in[0];
    float* out = (float*)d_out;
    // 16384 chains, 128 threads/block -> 128 blocks (<=1 block/SM, 1 warp/SMSP)
    hh_synaptic_kernel<<<128, 128>>>(z, out);
}

// round 2
// speedup vs baseline: 1.1805x; 1.1805x over previous
#include <cuda_runtime.h>

// HH_Synaptic: semi-implicit Hodgkin-Huxley + synapse integrator.
// z: (B=16, N=2000, L=1024) float32.  out: sigmoid((V - VT)/KP), same shape.
// One thread per (b, l) chain; 2000 serial steps per thread.
// Fast-math round: ex2.approx for all exponentials, rcp.approx for all
// divisions; 8-deep register prefetch ring for the z stream.

#define B_DIM 16
#define N_DIM 2000
#define L_DIM 1024
#define PF    8          // z prefetch distance (steps)

__device__ __forceinline__ float ex2f_(float x) {
    float r; asm("ex2.approx.f32 %0, %1;" : "=f"(r) : "f"(x)); return r;
}
__device__ __forceinline__ float rcpf_(float x) {
    float r; asm("rcp.approx.f32 %0, %1;" : "=f"(r) : "f"(x)); return r;
}

__global__ __launch_bounds__(128, 1)
void hh_synaptic_kernel(const float* __restrict__ z, float* __restrict__ out) {
    const int idx = blockIdx.x * blockDim.x + threadIdx.x;   // 0 .. 16383
    const int b = idx >> 10;
    const int l = idx & (L_DIM - 1);

    const float* zp = z   + (size_t)b * (N_DIM * L_DIM) + l;
    float*       op = out + (size_t)b * (N_DIM * L_DIM) + l;

    // State
    float V = -70.0f;
    float m = 0.0f, n = 0.0f, h = 1.0f, y = 0.0f;

    const float LOG2E = 1.4426950408889634f;
    const float c9    = LOG2E / 9.0f;    // exp(u/9)  -> ex2(u*c9)
    const float c12   = LOG2E / 12.0f;   // exp(u/12) -> ex2(u*c12)
    const float cAH   = 0.25f * expf(-56.0f / 12.0f);  // folded at compile time
    const float cSIG  = LOG2E / 3.0f;    // sigmoid arg scale: (V+20)/3 * log2e

    // k = 0 output: sigmoid((V + 20)/3)
    {
        float e = ex2f_(-(V + 20.0f) * cSIG);
        op[0] = rcpf_(1.0f + e);
    }

    // --- z prefetch ring: step k consumes z index (k-1) ---
    float zbuf[PF];
    #pragma unroll
    for (int j = 0; j < PF; ++j)
        zbuf[j] = __ldg(zp + (size_t)j * L_DIM);   // z indices 0..PF-1

    float* ol = op + L_DIM;

    #pragma unroll 2
    for (int k = 1; k < N_DIM; ++k) {
        float zc = zbuf[0];
        #pragma unroll
        for (int j = 0; j < PF - 1; ++j) zbuf[j] = zbuf[j + 1];
        // prefetch z index (k-1+PF), clamped in-bounds (clamped slots never consumed)
        int pidx = k - 1 + PF; if (pidx > N_DIM - 1) pidx = N_DIM - 1;
        zbuf[PF - 1] = __ldg(zp + (size_t)pidx * L_DIM);

        // ---- synapse update: fully independent of V path, start early ----
        float pY = 0.01f * (zc + 0.1f);             // DT/2*(ady + A_R), A_D=1
        float rY = rcpf_(1.0f + pY);
        float yn = fmaf(zc, 0.02f, y - pY * y) * rY;

        // ---- conductances / implicit V update ----
        float pow1 = 40.0f * (m * m * m) * h;        // GNA * m^3 * h
        float n2   = n * n;
        float pow2 = 35.0f * (n2 * n2);              // GK * n^4
        float G    = 0.01f * (pow1 + pow2 + (0.3f + y));  // DT/2*(...+GL+GS*y)
        float E    = fmaf(pow1, 55.0f, fmaf(pow2, -77.0f, -19.5f)); // GL*EL; VS=0
        float num  = fmaf(V, 1.0f - G, 0.02f * (E + 1.0f));         // DT*(E+IAPP)
        float Vn   = num * rcpf_(1.0f + G);

        // ---- rate constants: 4 independent ex2 off Vn ----
        float dv25 = Vn - 25.0f;
        float dv35 = Vn + 35.0f;
        float eN  = ex2f_(dv25 * c9);                // exp((V-25)/9)
        float eM  = ex2f_(dv35 * c9);                // exp((V+35)/9)
        float eHp = ex2f_( (Vn + 34.0f) * c12);      // exp((V+34)/12)
        float eHm = ex2f_(-(Vn + 34.0f) * c12);      // exp(-(V+34)/12)

        float aN, bN;
        if (dv25 == 0.0f) { aN = 0.18f; bN = 0.08f; }   // reference's exact patch
        else {
            float w = dv25 * rcpf_(eN - 1.0f);
            aN = 0.02f  * w * eN;
            bN = 0.002f * w;
        }
        float aM, bM;
        if (dv35 == 0.0f) { aM = 1.638f; bM = 1.16f; }
        else {
            float w = dv35 * rcpf_(eM - 1.0f);
            aM = 0.182f * w * eM;
            bM = 0.124f * w;
        }
        float bH = 0.25f * eHp;
        float aH = cAH  * eHm;                       // 0.25*exp(-(V+90)/12)

        // ---- semi-implicit gates: x' = (a*DT + (1-p)x)/(1+p), p = DT/2*(a+b) ----
        float pM = 0.01f * (aM + bM);
        float pN = 0.01f * (aN + bN);
        float pH = 0.01f * (aH + bH);
        float dM = 1.0f + pM, dN = 1.0f + pN;
        float rMN = rcpf_(dM * dN);                  // one rcp for both m and n
        m = fmaf(aM, 0.02f, m - pM * m) * (dN * rMN);
        n = fmaf(aN, 0.02f, n - pN * n) * (dM * rMN);
        h = fmaf(aH, 0.02f, h - pH * h) * rcpf_(1.0f + pH);
        y = yn;
        V = Vn;

        // ---- output sigmoid (no feedback into state) ----
        float e = ex2f_(-(V + 20.0f) * cSIG);
        *ol = rcpf_(1.0f + e);
        ol += L_DIM;
    }
}

extern "C" void kernel_launch(void* const* d_in, const int* in_sizes, int n_in,
                              void* d_out, int out_size) {
    const float* z = (const float*)d_in[0];
    float* out = (float*)d_out;
    // 16384 chains, 128 threads/block -> 128 blocks (1 warp per SMSP on 128 SMs)
    hh_synaptic_kernel<<<128, 128>>>(z, out);
}

// round 3
// speedup vs baseline: 1.8743x; 1.5877x over previous
#include <cuda_runtime.h>

// HH_Synaptic: semi-implicit Hodgkin-Huxley + synapse integrator.
// z: (B=16, N=2000, L=1024) float32.  out: sigmoid((V - VT)/KP), same shape.
// One thread per (b, l) chain; 2000 serial steps per thread.
// Round 3: branchless (FSEL) rate patches, shortened critical path,
// independent rcps per gate, x4 unroll so prefetch-ring shifts vanish.

#define N_DIM 2000
#define L_DIM 1024
#define PF    4          // z prefetch distance (steps)

__device__ __forceinline__ float ex2f_(float x) {
    float r; asm("ex2.approx.f32 %0, %1;" : "=f"(r) : "f"(x)); return r;
}
__device__ __forceinline__ float rcpf_(float x) {
    float r; asm("rcp.approx.f32 %0, %1;" : "=f"(r) : "f"(x)); return r;
}

__global__ __launch_bounds__(128, 1)
void hh_synaptic_kernel(const float* __restrict__ z, float* __restrict__ out) {
    const int idx = blockIdx.x * blockDim.x + threadIdx.x;   // 0 .. 16383
    const int b = idx >> 10;
    const int l = idx & (L_DIM - 1);

    const float* zp = z   + (size_t)b * (N_DIM * L_DIM) + l;
    float*       op = out + (size_t)b * (N_DIM * L_DIM) + l;

    // State
    float V = -70.0f;
    float m = 0.0f, n = 0.0f, h = 1.0f, y = 0.0f;

    const float LOG2E = 1.4426950408889634f;
    const float c9    = LOG2E / 9.0f;    // exp(u/9)  -> ex2(u*c9)
    const float c12   = LOG2E / 12.0f;   // exp(u/12) -> ex2(u*c12)
    const float cAH   = 0.25f * expf(-56.0f / 12.0f);
    const float cSIG  = LOG2E / 3.0f;    // sigmoid arg scale

    // k = 0 output
    {
        float e = ex2f_(-(V + 20.0f) * cSIG);
        op[0] = rcpf_(1.0f + e);
    }

    // z prefetch ring: step k consumes z index (k-1)
    float zbuf[PF];
    #pragma unroll
    for (int j = 0; j < PF; ++j)
        zbuf[j] = __ldg(zp + (size_t)j * L_DIM);

    float* ol = op + L_DIM;

    #pragma unroll 4
    for (int k = 1; k < N_DIM; ++k) {
        float zc = zbuf[0];
        #pragma unroll
        for (int j = 0; j < PF - 1; ++j) zbuf[j] = zbuf[j + 1];
        int pidx = min(k - 1 + PF, N_DIM - 1);       // clamped slots never consumed
        zbuf[PF - 1] = __ldg(zp + (size_t)pidx * L_DIM);

        // ---- synapse update (independent of V path) ----
        float pY = fmaf(0.01f, zc, 0.001f);          // DT/2*(z + A_R)
        float yn = fmaf(zc, 0.02f, fmaf(-pY, y, y)) * rcpf_(1.0f + pY);

        // ---- implicit V update ----
        float pow1 = 40.0f * (m * m * m) * h;        // GNA * m^3 * h
        float n2   = n * n;
        float pow2 = 35.0f * (n2 * n2);              // GK * n^4
        float G    = 0.01f * (pow1 + pow2 + (0.3f + y));
        float E    = fmaf(pow1, 55.0f, fmaf(pow2, -77.0f, -19.5f));
        float base = fmaf(0.02f, E, V + 0.02f);      // V + DT*(E+IAPP), parallel to G
        float Vn   = fmaf(-V, G, base) * rcpf_(1.0f + G);

        // ---- rate constants: 4 independent ex2 off Vn ----
        float dv25 = Vn - 25.0f;
        float dv35 = Vn + 35.0f;
        float eN  = ex2f_(dv25 * c9);
        float eM  = ex2f_(dv35 * c9);
        float eHp = ex2f_( (Vn + 34.0f) * c12);
        float eHm = ex2f_(-(Vn + 34.0f) * c12);

        // branchless singularity patches (FSEL, merges the whole step into one BB)
        bool sN = (dv25 == 0.0f);
        bool sM = (dv35 == 0.0f);
        float wN = dv25 * rcpf_(eN - 1.0f);
        float wM = dv35 * rcpf_(eM - 1.0f);
        float aN = sN ? 0.18f  : 0.02f  * wN * eN;
        float bN = sN ? 0.08f  : 0.002f * wN;
        float aM = sM ? 1.638f : 0.182f * wM * eM;
        float bM = sM ? 1.16f  : 0.124f * wM;
        float bH = 0.25f * eHp;
        float aH = cAH  * eHm;

        // ---- semi-implicit gates: x' = (a*DT + (1-p)x) * rcp(1+p) ----
        float pM = 0.01f * (aM + bM);
        float pN = 0.01f * (aN + bN);
        float pH = 0.01f * (aH + bH);
        m = fmaf(aM, 0.02f, fmaf(-pM, m, m)) * rcpf_(1.0f + pM);
        n = fmaf(aN, 0.02f, fmaf(-pN, n, n)) * rcpf_(1.0f + pN);
        h = fmaf(aH, 0.02f, fmaf(-pH, h, h)) * rcpf_(1.0f + pH);
        y = yn;
        V = Vn;

        // ---- output sigmoid (off the recurrence) ----
        float e = ex2f_(-(V + 20.0f) * cSIG);
        *ol = rcpf_(1.0f + e);
        ol += L_DIM;
    }
}

extern "C" void kernel_launch(void* const* d_in, const int* in_sizes, int n_in,
                              void* d_out, int out_size) {
    const float* z = (const float*)d_in[0];
    float* out = (float*)d_out;
    hh_synaptic_kernel<<<128, 128>>>(z, out);
}